// round 12
// baseline (speedup 1.0000x reference)
#include <cuda_runtime.h>
#include <cuda_bf16.h>
#include <cuda_fp16.h>
#include <mma.h>

using namespace nvcuda;

// ---------------------------------------------------------------------------
// SAGE 2-layer GraphSAGE, mean aggregation.
//   agg1 = mean_{src->i} x[src];  h = relu(x@Ws1 + agg1@Wn1 + b1)
//   out  = h@Ws2 + mean_{src->i} (h@Wn2)[src] + b2   (aggregation is linear)
// fp16 data path (fp32 accumulation), wmma tensor-core GEMMs.
// R12: aggregation-1 fused into gemm1 (smem AggS), A-fragments read directly
// from global (padded buffers), no As staging.
// RULES: never pass __device__ globals as kernel args (R5 lesson).
// ---------------------------------------------------------------------------

#define N_NODES 100000
#define N_EDGES 1600000
#define D_IN    128
#define D_HID   128
#define D_OUT   64

#define SCAN_NB ((N_NODES + 127) / 128)   // 782 blocks of 128 nodes
#define XCONV_T (N_NODES * D_IN / 4)      // 3.2M float4-threads for x->fp16
#define PAD_ROWS 128                      // row padding for OOB-safe frag loads

// -------------------- device scratch (no allocations allowed) --------------
__device__ int    g_i64;                // 1 if edge indices are int64
__device__ int    g_deg[N_NODES];
__device__ int    g_rowptr[N_NODES + 1];
__device__ int    g_cursor[N_NODES];
__device__ int    g_bsum[SCAN_NB];
__device__ int    g_boff[SCAN_NB];
__device__ int    g_csrsrc[N_EDGES];
__device__ __half g_xh[(size_t)(N_NODES + PAD_ROWS) * D_IN];   // fp16 x (padded)
__device__ __half g_hh[(size_t)(N_NODES + PAD_ROWS) * D_HID];  // fp16 hidden (padded)
__device__ __half g_th[(size_t)N_NODES * D_OUT];   // h @ W_neigh2, fp16
__device__ __half g_B1h[256 * 128];                // [Ws1 ; Wn1] K-major
__device__ __half g_B2h[128 * 128];                // [Ws2 | Wn2] K-major

// -------------------- fused init: deg-zero + detect + x->h + W->h ----------
// int64 values in [0, 2^31) have zero odd 32-bit words (little-endian).
__global__ void k_init(const void* srcbuf, const float* __restrict__ x,
                       const float* __restrict__ Ws1,
                       const float* __restrict__ Wn1,
                       const float* __restrict__ Ws2,
                       const float* __restrict__ Wn2) {
    int i = blockIdx.x * blockDim.x + threadIdx.x;
    if (i < N_NODES) g_deg[i] = 0;
    if (i < XCONV_T) {                       // x -> fp16 (one float4/thread)
        float4 v = ((const float4*)x)[i];
        __half2 a = __floats2half2_rn(v.x, v.y);
        __half2 b = __floats2half2_rn(v.z, v.w);
        uint2 u;
        u.x = *reinterpret_cast<unsigned*>(&a);
        u.y = *reinterpret_cast<unsigned*>(&b);
        ((uint2*)g_xh)[i] = u;
    }
    if (i < 49152) {                         // weights -> fp16
        if (i < 16384) {
            g_B1h[i] = __float2half_rn(Ws1[i]);
        } else if (i < 32768) {
            g_B1h[i] = __float2half_rn(Wn1[i - 16384]);
        } else {
            int t = i - 32768;
            int k = t >> 7, n = t & 127;
            float v = (n < 64) ? Ws2[k * 64 + n] : Wn2[k * 64 + (n - 64)];
            g_B2h[t] = __float2half_rn(v);
        }
    }
    if (blockIdx.x == 0) {                   // dtype detect
        const int* w = (const int*)srcbuf;
        __shared__ int odd_nz;
        if (threadIdx.x == 0) odd_nz = 0;
        __syncthreads();
        int bad = 0;
        for (int k = threadIdx.x; k < 1024; k += blockDim.x)
            if (w[2 * k + 1] != 0) bad = 1;  // stays within 8KB of buffer
        if (bad) atomicOr(&odd_nz, 1);
        __syncthreads();
        if (threadIdx.x == 0) g_i64 = (odd_nz == 0) ? 1 : 0;
    }
}

__device__ __forceinline__ int idx_at(const void* p, int e, int i64) {
    return i64 ? (int)((const long long*)p)[e] : ((const int*)p)[e];
}

// -------------------- CSR build ---------------------------------------------
__global__ void k_hist(const void* dst) {
    int e = blockIdx.x * blockDim.x + threadIdx.x;
    int i64 = g_i64;
    if (e < N_EDGES) {
        int d = idx_at(dst, e, i64);
        if (d >= 0 && d < N_NODES) atomicAdd(&g_deg[d], 1);
    }
}

__global__ __launch_bounds__(128) void k_scan_partial() {
    __shared__ int s[128];
    int t = threadIdx.x;
    int i = blockIdx.x * 128 + t;
    int d = (i < N_NODES) ? g_deg[i] : 0;
    s[t] = d;
    __syncthreads();
#pragma unroll
    for (int off = 1; off < 128; off <<= 1) {
        int v = (t >= off) ? s[t - off] : 0;
        __syncthreads();
        s[t] += v;
        __syncthreads();
    }
    if (t == 127) g_bsum[blockIdx.x] = s[127];
}

__global__ __launch_bounds__(1024) void k_scan_tops() {
    __shared__ int s[1024];
    int t = threadIdx.x;
    int v0 = (t < SCAN_NB) ? g_bsum[t] : 0;
    s[t] = v0;
    __syncthreads();
#pragma unroll
    for (int off = 1; off < 1024; off <<= 1) {
        int v = (t >= off) ? s[t - off] : 0;
        __syncthreads();
        s[t] += v;
        __syncthreads();
    }
    if (t < SCAN_NB) g_boff[t] = s[t] - v0;        // exclusive
    if (t == 1023) g_rowptr[N_NODES] = s[1023];    // grand total
}

__global__ __launch_bounds__(128) void k_scan_fill() {
    __shared__ int s[128];
    int t = threadIdx.x;
    int i = blockIdx.x * 128 + t;
    int d = (i < N_NODES) ? g_deg[i] : 0;
    s[t] = d;
    __syncthreads();
#pragma unroll
    for (int off = 1; off < 128; off <<= 1) {
        int v = (t >= off) ? s[t - off] : 0;
        __syncthreads();
        s[t] += v;
        __syncthreads();
    }
    if (i < N_NODES) {
        int p = g_boff[blockIdx.x] + s[t] - d;     // exclusive prefix
        g_rowptr[i] = p;
        g_cursor[i] = p;
    }
}

__global__ void k_scatter(const void* src, const void* dst) {
    int e = blockIdx.x * blockDim.x + threadIdx.x;
    int i64 = g_i64;
    if (e < N_EDGES) {
        int d = idx_at(dst, e, i64);
        int s = idx_at(src, e, i64);
        if (d >= 0 && d < N_NODES && s >= 0 && s < N_NODES) {
            int pos = atomicAdd(&g_cursor[d], 1);
            g_csrsrc[pos] = s;
        }
    }
}

// -------------------- layer-2 aggregation (fp16 payload, fp32 accum) --------
// one warp per node over g_th; row = 64 halfs = 32 half2 lanes
__global__ void k_agg64h(float* __restrict__ out) {
    int gtid = blockIdx.x * blockDim.x + threadIdx.x;
    int node = gtid >> 5;
    int lane = gtid & 31;
    if (node >= N_NODES) return;
    int beg = g_rowptr[node];
    int end = g_rowptr[node + 1];
    const __half2* th = (const __half2*)g_th;
    float ax0 = 0.f, ay0 = 0.f, ax1 = 0.f, ay1 = 0.f;
    int j = beg;
    for (; j + 1 < end; j += 2) {
        int s0 = g_csrsrc[j];
        int s1 = g_csrsrc[j + 1];
        float2 v0 = __half22float2(th[(size_t)s0 * 32 + lane]);
        float2 v1 = __half22float2(th[(size_t)s1 * 32 + lane]);
        ax0 += v0.x; ay0 += v0.y;
        ax1 += v1.x; ay1 += v1.y;
    }
    if (j < end) {
        int s0 = g_csrsrc[j];
        float2 v0 = __half22float2(th[(size_t)s0 * 32 + lane]);
        ax0 += v0.x; ay0 += v0.y;
    }
    int deg = end - beg;
    float inv = 1.0f / (float)(deg > 0 ? deg : 1);
    float2* o2 = (float2*)out;
    float2 cur = o2[(size_t)node * 32 + lane];
    cur.x += (ax0 + ax1) * inv;
    cur.y += (ay0 + ay1) * inv;
    o2[(size_t)node * 32 + lane] = cur;
}

// -------------------- fused agg1 + GEMM1 ------------------------------------
// Block: 256 threads = 8 warps.  Phase 1: aggregate the block's 128 nodes
// into AggS (fp16, 32KB).  Phase 2: g_hh = relu([xh | AggS] @ B1h + b1),
// warp (warpM 0..3, warpN 0..1) computes 32x64 via 2x4 wmma frags.
// A-fragments: kk<8 direct from global g_xh (padded), kk>=8 from AggS.
__global__ __launch_bounds__(256) void k_gemm1h(const float* __restrict__ b1) {
    __shared__ __align__(16) __half AggS[128][128];   // 32KB
    __shared__ __align__(16) __half Bs[2][16][128];   // 8KB
    __shared__ __align__(16) float  Cst[8][256];      // 8KB
    const int tid = threadIdx.x;
    const int warp = tid >> 5;
    const int lane = tid & 31;
    const int warpM = warp & 3;   // 0..3
    const int warpN = warp >> 2;  // 0..1
    const int rowBase = blockIdx.x * 128;

    // ---- phase 1: aggregate 16 contiguous nodes per warp into AggS
    {
        const uint2* xh = (const uint2*)g_xh;
        for (int i = 0; i < 16; i++) {
            int nl = warp * 16 + i;          // local row 0..127
            int node = rowBase + nl;
            float ax0 = 0.f, ay0 = 0.f, az0 = 0.f, aw0 = 0.f;
            float ax1 = 0.f, ay1 = 0.f, az1 = 0.f, aw1 = 0.f;
            int deg = 0;
            if (node < N_NODES) {
                int beg = g_rowptr[node];
                int end = g_rowptr[node + 1];
                deg = end - beg;
                int j = beg;
                for (; j + 1 < end; j += 2) {
                    int s0 = g_csrsrc[j];
                    int s1 = g_csrsrc[j + 1];
                    uint2 u0 = xh[(size_t)s0 * 32 + lane];
                    uint2 u1 = xh[(size_t)s1 * 32 + lane];
                    float2 l0 = __half22float2(*reinterpret_cast<__half2*>(&u0.x));
                    float2 h0 = __half22float2(*reinterpret_cast<__half2*>(&u0.y));
                    float2 l1 = __half22float2(*reinterpret_cast<__half2*>(&u1.x));
                    float2 h1 = __half22float2(*reinterpret_cast<__half2*>(&u1.y));
                    ax0 += l0.x; ay0 += l0.y; az0 += h0.x; aw0 += h0.y;
                    ax1 += l1.x; ay1 += l1.y; az1 += h1.x; aw1 += h1.y;
                }
                if (j < end) {
                    int s0 = g_csrsrc[j];
                    uint2 u0 = xh[(size_t)s0 * 32 + lane];
                    float2 l0 = __half22float2(*reinterpret_cast<__half2*>(&u0.x));
                    float2 h0 = __half22float2(*reinterpret_cast<__half2*>(&u0.y));
                    ax0 += l0.x; ay0 += l0.y; az0 += h0.x; aw0 += h0.y;
                }
            }
            float inv = 1.0f / (float)(deg > 0 ? deg : 1);
            __half2 p0 = __floats2half2_rn((ax0 + ax1) * inv, (ay0 + ay1) * inv);
            __half2 p1 = __floats2half2_rn((az0 + az1) * inv, (aw0 + aw1) * inv);
            uint2 u;
            u.x = *reinterpret_cast<unsigned*>(&p0);
            u.y = *reinterpret_cast<unsigned*>(&p1);
            ((uint2*)&AggS[nl][0])[lane] = u;   // halfs 4*lane..4*lane+3
        }
    }

    // ---- stage B tile 0
    const int bRow = tid >> 4;          // 0..15
    const int bCol8 = (tid & 15) * 8;   // 0..120
    {
        uint4 bv = *(const uint4*)(g_B1h + (size_t)bRow * 128 + bCol8);
        *(uint4*)&Bs[0][bRow][bCol8] = bv;
    }
    __syncthreads();   // publish AggS + Bs[0]

    wmma::fragment<wmma::accumulator, 16, 16, 16, float> acc[2][4];
#pragma unroll
    for (int i = 0; i < 2; i++)
#pragma unroll
        for (int j = 0; j < 4; j++) wmma::fill_fragment(acc[i][j], 0.f);

    for (int kk = 0; kk < 16; kk++) {
        const int cur = kk & 1;
        const int nxt = cur ^ 1;
        if (kk + 1 < 16) {
            int kn = kk + 1;
            uint4 bv = *(const uint4*)(g_B1h + (size_t)(kn * 16 + bRow) * 128 + bCol8);
            *(uint4*)&Bs[nxt][bRow][bCol8] = bv;
        }

        wmma::fragment<wmma::matrix_b, 16, 16, 16, __half, wmma::row_major> bf[4];
#pragma unroll
        for (int j = 0; j < 4; j++)
            wmma::load_matrix_sync(bf[j], &Bs[cur][0][warpN * 64 + j * 16], 128);
#pragma unroll
        for (int i = 0; i < 2; i++) {
            wmma::fragment<wmma::matrix_a, 16, 16, 16, __half, wmma::row_major> af;
            if (kk < 8) {
                const __half* Ap = g_xh + (size_t)(rowBase + warpM * 32 + i * 16) * 128
                                   + kk * 16;          // padded: OOB rows safe
                wmma::load_matrix_sync(af, Ap, 128);
            } else {
                wmma::load_matrix_sync(af, &AggS[warpM * 32 + i * 16][(kk - 8) * 16], 128);
            }
#pragma unroll
            for (int j = 0; j < 4; j++)
                wmma::mma_sync(acc[i][j], af, bf[j], acc[i][j]);
        }
        __syncthreads();
    }

    // ---- epilogue: bias + relu -> fp16 g_hh
#pragma unroll
    for (int i = 0; i < 2; i++)
#pragma unroll
        for (int j = 0; j < 4; j++) {
            __syncwarp();
            wmma::store_matrix_sync(&Cst[warp][0], acc[i][j], 16, wmma::mem_row_major);
            __syncwarp();
            int r = rowBase + warpM * 32 + i * 16 + (lane >> 1);
            int c = warpN * 64 + j * 16 + (lane & 1) * 8;
            if (r < N_NODES) {
                const float* row = &Cst[warp][(lane >> 1) * 16 + (lane & 1) * 8];
                float v[8];
#pragma unroll
                for (int q = 0; q < 8; q++) {
                    float z = row[q] + b1[c + q];
                    v[q] = z > 0.f ? z : 0.f;
                }
                __half2 p0 = __floats2half2_rn(v[0], v[1]);
                __half2 p1 = __floats2half2_rn(v[2], v[3]);
                __half2 p2 = __floats2half2_rn(v[4], v[5]);
                __half2 p3 = __floats2half2_rn(v[6], v[7]);
                uint4 u;
                u.x = *reinterpret_cast<unsigned*>(&p0);
                u.y = *reinterpret_cast<unsigned*>(&p1);
                u.z = *reinterpret_cast<unsigned*>(&p2);
                u.w = *reinterpret_cast<unsigned*>(&p3);
                *(uint4*)(g_hh + (size_t)r * 128 + c) = u;
            }
        }
}

// -------------------- GEMM2: [self | neigh] = g_hh @ g_B2h, K=128 -----------
// A-fragments direct from global g_hh (padded).  warpN==0: +b2 -> out fp32.
// warpN==1: -> g_th fp16.
__global__ __launch_bounds__(256) void k_gemm2h(const float* __restrict__ b2,
                                                float* __restrict__ out) {
    __shared__ __align__(16) __half Bs[2][16][128];   // 8KB
    __shared__ __align__(16) float  Cst[8][256];      // 8KB
    const int tid = threadIdx.x;
    const int warp = tid >> 5;
    const int lane = tid & 31;
    const int warpM = warp & 3;
    const int warpN = warp >> 2;
    const int rowBase = blockIdx.x * 128;

    wmma::fragment<wmma::accumulator, 16, 16, 16, float> acc[2][4];
#pragma unroll
    for (int i = 0; i < 2; i++)
#pragma unroll
        for (int j = 0; j < 4; j++) wmma::fill_fragment(acc[i][j], 0.f);

    const int bRow = tid >> 4;
    const int bCol8 = (tid & 15) * 8;
    {
        uint4 bv = *(const uint4*)(g_B2h + (size_t)bRow * 128 + bCol8);
        *(uint4*)&Bs[0][bRow][bCol8] = bv;
    }
    __syncthreads();

    for (int kk = 0; kk < 8; kk++) {
        const int cur = kk & 1;
        const int nxt = cur ^ 1;
        if (kk + 1 < 8) {
            int kn = kk + 1;
            uint4 bv = *(const uint4*)(g_B2h + (size_t)(kn * 16 + bRow) * 128 + bCol8);
            *(uint4*)&Bs[nxt][bRow][bCol8] = bv;
        }

        wmma::fragment<wmma::matrix_b, 16, 16, 16, __half, wmma::row_major> bf[4];
#pragma unroll
        for (int j = 0; j < 4; j++)
            wmma::load_matrix_sync(bf[j], &Bs[cur][0][warpN * 64 + j * 16], 128);
#pragma unroll
        for (int i = 0; i < 2; i++) {
            wmma::fragment<wmma::matrix_a, 16, 16, 16, __half, wmma::row_major> af;
            const __half* Ap = g_hh + (size_t)(rowBase + warpM * 32 + i * 16) * 128
                               + kk * 16;              // padded: OOB rows safe
            wmma::load_matrix_sync(af, Ap, 128);
#pragma unroll
            for (int j = 0; j < 4; j++)
                wmma::mma_sync(acc[i][j], af, bf[j], acc[i][j]);
        }
        __syncthreads();
    }

#pragma unroll
    for (int i = 0; i < 2; i++)
#pragma unroll
        for (int j = 0; j < 4; j++) {
            __syncwarp();
            wmma::store_matrix_sync(&Cst[warp][0], acc[i][j], 16, wmma::mem_row_major);
            __syncwarp();
            int r = rowBase + warpM * 32 + i * 16 + (lane >> 1);
            int cc = j * 16 + (lane & 1) * 8;     // 0..63 within half
            if (r < N_NODES) {
                const float* row = &Cst[warp][(lane >> 1) * 16 + (lane & 1) * 8];
                if (warpN == 0) {                 // self half -> fp32 out
                    float v[8];
#pragma unroll
                    for (int q = 0; q < 8; q++) v[q] = row[q] + b2[cc + q];
                    float4* dst4 = (float4*)(out + (size_t)r * D_OUT + cc);
                    dst4[0] = make_float4(v[0], v[1], v[2], v[3]);
                    dst4[1] = make_float4(v[4], v[5], v[6], v[7]);
                } else {                          // neigh half -> fp16 g_th
                    __half2 p0 = __floats2half2_rn(row[0], row[1]);
                    __half2 p1 = __floats2half2_rn(row[2], row[3]);
                    __half2 p2 = __floats2half2_rn(row[4], row[5]);
                    __half2 p3 = __floats2half2_rn(row[6], row[7]);
                    uint4 u;
                    u.x = *reinterpret_cast<unsigned*>(&p0);
                    u.y = *reinterpret_cast<unsigned*>(&p1);
                    u.z = *reinterpret_cast<unsigned*>(&p2);
                    u.w = *reinterpret_cast<unsigned*>(&p3);
                    *(uint4*)(g_th + (size_t)r * D_OUT + cc) = u;
                }
            }
        }
}

// ---------------------------------------------------------------------------
extern "C" void kernel_launch(void* const* d_in, const int* in_sizes, int n_in,
                              void* d_out, int out_size) {
    const float* x   = (const float*)d_in[0];
    const void*  src = d_in[1];
    const void*  dst = d_in[2];
    const float* Ws1 = (const float*)d_in[3];
    const float* Wn1 = (const float*)d_in[4];
    const float* b1  = (const float*)d_in[5];
    const float* Ws2 = (const float*)d_in[6];
    const float* Wn2 = (const float*)d_in[7];
    const float* b2  = (const float*)d_in[8];
    float* out = (float*)d_out;

    // 1) fused init (deg-zero + dtype detect + x->fp16 + W->fp16)
    k_init<<<(XCONV_T + 255) / 256, 256>>>(src, x, Ws1, Wn1, b1 ? Ws2 : Ws2, Wn2);

    // 2) CSR build
    k_hist<<<(N_EDGES + 255) / 256, 256>>>(dst);
    k_scan_partial<<<SCAN_NB, 128>>>();
    k_scan_tops<<<1, 1024>>>();
    k_scan_fill<<<SCAN_NB, 128>>>();
    k_scatter<<<(N_EDGES + 255) / 256, 256>>>(src, dst);

    // 3) layer 1 (aggregation fused into GEMM1)
    k_gemm1h<<<(N_NODES + 127) / 128, 256>>>(b1);

    // 4) layer 2 (transform first, aggregate fp16 64-wide afterwards)
    k_gemm2h<<<(N_NODES + 127) / 128, 256>>>(b2, out);
    k_agg64h<<<(N_NODES * 32 + 255) / 256, 256>>>(out);
}

// round 15
// speedup vs baseline: 1.1552x; 1.1552x over previous
#include <cuda_runtime.h>
#include <cuda_bf16.h>
#include <cuda_fp16.h>
#include <mma.h>

using namespace nvcuda;

// ---------------------------------------------------------------------------
// SAGE 2-layer GraphSAGE, mean aggregation.
//   agg1 = mean_{src->i} x[src];  h = relu(x@Ws1 + agg1@Wn1 + b1)
//   out  = h@Ws2 + mean_{src->i} (h@Wn2)[src] + b2   (aggregation is linear)
// fp16 data path (fp32 accumulation), wmma tensor-core GEMMs (R10 config —
// best measured), single-pass decoupled-lookback scan, fused init.
// RULES: never pass __device__ globals as kernel args (R5 lesson).
//        gather phases stay in dedicated high-occupancy kernels (R12 lesson).
// ---------------------------------------------------------------------------

#define N_NODES 100000
#define N_EDGES 1600000
#define D_IN    128
#define D_HID   128
#define D_OUT   64

#define SCAN_NB ((N_NODES + 127) / 128)   // 782 blocks of 128 nodes
#define XCONV_T (N_NODES * D_IN / 4)      // 3.2M float4-threads for x->fp16

// -------------------- device scratch (no allocations allowed) --------------
__device__ int    g_i64;                // 1 if edge indices are int64
__device__ int    g_deg[N_NODES];
__device__ int    g_rowptr[N_NODES + 1];
__device__ int    g_cursor[N_NODES];
__device__ int    g_bsum[SCAN_NB];
__device__ int    g_flag[SCAN_NB];
__device__ int    g_csrsrc[N_EDGES];
__device__ __half g_xh[(size_t)N_NODES * D_IN];    // fp16 copy of x
__device__ __half g_aggh[(size_t)N_NODES * D_IN];  // fp16 layer-1 mean
__device__ __half g_hh[(size_t)N_NODES * D_HID];   // fp16 hidden
__device__ __half g_th[(size_t)N_NODES * D_OUT];   // h @ W_neigh2, fp16
__device__ __half g_B1h[256 * 128];                // [Ws1 ; Wn1] K-major
__device__ __half g_B2h[128 * 128];                // [Ws2 | Wn2] K-major

// -------------------- fused init: zero deg/flags + detect + x->h + W->h ----
// int64 values in [0, 2^31) have zero odd 32-bit words (little-endian).
__global__ void k_init(const void* srcbuf, const float* __restrict__ x,
                       const float* __restrict__ Ws1,
                       const float* __restrict__ Wn1,
                       const float* __restrict__ Ws2,
                       const float* __restrict__ Wn2) {
    int i = blockIdx.x * blockDim.x + threadIdx.x;
    if (i < N_NODES) g_deg[i] = 0;
    if (i < SCAN_NB) g_flag[i] = 0;
    if (i < XCONV_T) {                       // x -> fp16 (one float4/thread)
        float4 v = ((const float4*)x)[i];
        __half2 a = __floats2half2_rn(v.x, v.y);
        __half2 b = __floats2half2_rn(v.z, v.w);
        uint2 u;
        u.x = *reinterpret_cast<unsigned*>(&a);
        u.y = *reinterpret_cast<unsigned*>(&b);
        ((uint2*)g_xh)[i] = u;
    }
    if (i < 49152) {                         // weights -> fp16
        if (i < 16384) {
            g_B1h[i] = __float2half_rn(Ws1[i]);
        } else if (i < 32768) {
            g_B1h[i] = __float2half_rn(Wn1[i - 16384]);
        } else {
            int t = i - 32768;
            int k = t >> 7, n = t & 127;
            float v = (n < 64) ? Ws2[k * 64 + n] : Wn2[k * 64 + (n - 64)];
            g_B2h[t] = __float2half_rn(v);
        }
    }
    if (blockIdx.x == 0) {                   // dtype detect
        const int* w = (const int*)srcbuf;
        __shared__ int odd_nz;
        if (threadIdx.x == 0) odd_nz = 0;
        __syncthreads();
        int bad = 0;
        for (int k = threadIdx.x; k < 1024; k += blockDim.x)
            if (w[2 * k + 1] != 0) bad = 1;  // stays within 8KB of buffer
        if (bad) atomicOr(&odd_nz, 1);
        __syncthreads();
        if (threadIdx.x == 0) g_i64 = (odd_nz == 0) ? 1 : 0;
    }
}

__device__ __forceinline__ int idx_at(const void* p, int e, int i64) {
    return i64 ? (int)((const long long*)p)[e] : ((const int*)p)[e];
}

// -------------------- CSR build ---------------------------------------------
__global__ void k_hist(const void* dst) {
    int e = blockIdx.x * blockDim.x + threadIdx.x;
    int i64 = g_i64;
    if (e < N_EDGES) {
        int d = idx_at(dst, e, i64);
        if (d >= 0 && d < N_NODES) atomicAdd(&g_deg[d], 1);
    }
}

// single-pass decoupled-lookback scan: rowptr/cursor in ONE kernel.
// All 782 blocks (128 thr, few regs) are co-resident -> spin-wait is safe.
__global__ __launch_bounds__(128) void k_scan_one() {
    __shared__ int s[128];
    __shared__ int excl_sh;
    const int b = blockIdx.x;
    const int t = threadIdx.x;
    int i = b * 128 + t;
    int d = (i < N_NODES) ? g_deg[i] : 0;
    s[t] = d;
    __syncthreads();
#pragma unroll
    for (int off = 1; off < 128; off <<= 1) {
        int v = (t >= off) ? s[t - off] : 0;
        __syncthreads();
        s[t] += v;
        __syncthreads();
    }
    const int total = s[127];
    if (t == 0) {
        g_bsum[b] = total;
        __threadfence();
        atomicExch(&g_flag[b], 1);           // publish
    }
    // lookback: warp 0 sums predecessors' aggregates
    if (t < 32) {
        int acc = 0;
        for (int j = t; j < b; j += 32) {
            while (__ldcg(&g_flag[j]) == 0) {}   // spin (L2 read)
            acc += __ldcg(&g_bsum[j]);
        }
#pragma unroll
        for (int o = 16; o > 0; o >>= 1)
            acc += __shfl_down_sync(0xFFFFFFFFu, acc, o);
        if (t == 0) excl_sh = acc;
    }
    __syncthreads();
    const int excl = excl_sh;
    if (i < N_NODES) {
        int p = excl + s[t] - d;             // exclusive prefix
        g_rowptr[i] = p;
        g_cursor[i] = p;
    }
    if (b == SCAN_NB - 1 && t == 127) g_rowptr[N_NODES] = excl + total;
}

__global__ void k_scatter(const void* src, const void* dst) {
    int e = blockIdx.x * blockDim.x + threadIdx.x;
    int i64 = g_i64;
    if (e < N_EDGES) {
        int d = idx_at(dst, e, i64);
        int s = idx_at(src, e, i64);
        if (d >= 0 && d < N_NODES && s >= 0 && s < N_NODES) {
            int pos = atomicAdd(&g_cursor[d], 1);
            g_csrsrc[pos] = s;
        }
    }
}

// -------------------- aggregation kernels (fp16 payload, fp32 accum) --------
// layer 1: one warp per node; row = 128 halfs = 32 uint2 lanes (8B/lane)
__global__ void k_agg128h() {
    int gtid = blockIdx.x * blockDim.x + threadIdx.x;
    int node = gtid >> 5;
    int lane = gtid & 31;
    if (node >= N_NODES) return;
    int beg = g_rowptr[node];
    int end = g_rowptr[node + 1];
    const uint2* xh = (const uint2*)g_xh;
    float ax0 = 0.f, ay0 = 0.f, az0 = 0.f, aw0 = 0.f;
    float ax1 = 0.f, ay1 = 0.f, az1 = 0.f, aw1 = 0.f;
    int j = beg;
    for (; j + 1 < end; j += 2) {
        int s0 = g_csrsrc[j];
        int s1 = g_csrsrc[j + 1];
        uint2 u0 = xh[(size_t)s0 * 32 + lane];
        uint2 u1 = xh[(size_t)s1 * 32 + lane];
        float2 l0 = __half22float2(*reinterpret_cast<__half2*>(&u0.x));
        float2 h0 = __half22float2(*reinterpret_cast<__half2*>(&u0.y));
        float2 l1 = __half22float2(*reinterpret_cast<__half2*>(&u1.x));
        float2 h1 = __half22float2(*reinterpret_cast<__half2*>(&u1.y));
        ax0 += l0.x; ay0 += l0.y; az0 += h0.x; aw0 += h0.y;
        ax1 += l1.x; ay1 += l1.y; az1 += h1.x; aw1 += h1.y;
    }
    if (j < end) {
        int s0 = g_csrsrc[j];
        uint2 u0 = xh[(size_t)s0 * 32 + lane];
        float2 l0 = __half22float2(*reinterpret_cast<__half2*>(&u0.x));
        float2 h0 = __half22float2(*reinterpret_cast<__half2*>(&u0.y));
        ax0 += l0.x; ay0 += l0.y; az0 += h0.x; aw0 += h0.y;
    }
    int deg = end - beg;
    float inv = 1.0f / (float)(deg > 0 ? deg : 1);
    __half2 p0 = __floats2half2_rn((ax0 + ax1) * inv, (ay0 + ay1) * inv);
    __half2 p1 = __floats2half2_rn((az0 + az1) * inv, (aw0 + aw1) * inv);
    uint2 u;
    u.x = *reinterpret_cast<unsigned*>(&p0);
    u.y = *reinterpret_cast<unsigned*>(&p1);
    ((uint2*)g_aggh)[(size_t)node * 32 + lane] = u;
}

// layer 2: one warp per node over g_th; row = 64 halfs = 32 half2 lanes
__global__ void k_agg64h(float* __restrict__ out) {
    int gtid = blockIdx.x * blockDim.x + threadIdx.x;
    int node = gtid >> 5;
    int lane = gtid & 31;
    if (node >= N_NODES) return;
    int beg = g_rowptr[node];
    int end = g_rowptr[node + 1];
    const __half2* th = (const __half2*)g_th;
    float ax0 = 0.f, ay0 = 0.f, ax1 = 0.f, ay1 = 0.f;
    int j = beg;
    for (; j + 1 < end; j += 2) {
        int s0 = g_csrsrc[j];
        int s1 = g_csrsrc[j + 1];
        float2 v0 = __half22float2(th[(size_t)s0 * 32 + lane]);
        float2 v1 = __half22float2(th[(size_t)s1 * 32 + lane]);
        ax0 += v0.x; ay0 += v0.y;
        ax1 += v1.x; ay1 += v1.y;
    }
    if (j < end) {
        int s0 = g_csrsrc[j];
        float2 v0 = __half22float2(th[(size_t)s0 * 32 + lane]);
        ax0 += v0.x; ay0 += v0.y;
    }
    int deg = end - beg;
    float inv = 1.0f / (float)(deg > 0 ? deg : 1);
    float2* o2 = (float2*)out;
    float2 cur = o2[(size_t)node * 32 + lane];
    cur.x += (ax0 + ax1) * inv;
    cur.y += (ay0 + ay1) * inv;
    o2[(size_t)node * 32 + lane] = cur;
}

// -------------------- wmma tensor-core GEMMs (R10 config) -------------------
// Block: 256 threads = 8 warps, 4 (M) x 2 (N); each warp does 32x64 via
// 2x4 fragments of 16x16x16 (fp16 in, fp32 acc).  BM=128, BN=128.

// g_hh = relu( [g_xh | g_aggh] @ g_B1h + b1 )  : K = 256
__global__ __launch_bounds__(256) void k_gemm1h(const float* __restrict__ b1) {
    __shared__ __align__(16) __half As[128][16];
    __shared__ __align__(16) __half Bs[16][128];
    __shared__ __align__(16) float  Cst[8][256];
    const int tid = threadIdx.x;
    const int warp = tid >> 5;
    const int lane = tid & 31;
    const int warpM = warp & 3;   // 0..3
    const int warpN = warp >> 2;  // 0..1
    const int rowBase = blockIdx.x * 128;

    wmma::fragment<wmma::accumulator, 16, 16, 16, float> acc[2][4];
#pragma unroll
    for (int i = 0; i < 2; i++)
#pragma unroll
        for (int j = 0; j < 4; j++) wmma::fill_fragment(acc[i][j], 0.f);

    const int aRow = tid >> 1;          // 0..127
    const int aCol8 = (tid & 1) * 8;    // 0 / 8
    int arow_g = rowBase + aRow;
    if (arow_g >= N_NODES) arow_g = N_NODES - 1;
    const int bRow = tid >> 4;          // 0..15
    const int bCol8 = (tid & 15) * 8;   // 0..120

    for (int kk = 0; kk < 16; kk++) {
        const __half* Ap = (kk < 8)
            ? (g_xh   + (size_t)arow_g * 128 + kk * 16 + aCol8)
            : (g_aggh + (size_t)arow_g * 128 + (kk - 8) * 16 + aCol8);
        uint4 av = *(const uint4*)Ap;
        uint4 bv = *(const uint4*)(g_B1h + (size_t)(kk * 16 + bRow) * 128 + bCol8);
        __syncthreads();
        *(uint4*)&As[aRow][aCol8] = av;
        *(uint4*)&Bs[bRow][bCol8] = bv;
        __syncthreads();

        wmma::fragment<wmma::matrix_b, 16, 16, 16, __half, wmma::row_major> bf[4];
#pragma unroll
        for (int j = 0; j < 4; j++)
            wmma::load_matrix_sync(bf[j], &Bs[0][warpN * 64 + j * 16], 128);
#pragma unroll
        for (int i = 0; i < 2; i++) {
            wmma::fragment<wmma::matrix_a, 16, 16, 16, __half, wmma::row_major> af;
            wmma::load_matrix_sync(af, &As[warpM * 32 + i * 16][0], 16);
#pragma unroll
            for (int j = 0; j < 4; j++)
                wmma::mma_sync(acc[i][j], af, bf[j], acc[i][j]);
        }
    }

    // epilogue: bias + relu -> fp16 g_hh
#pragma unroll
    for (int i = 0; i < 2; i++)
#pragma unroll
        for (int j = 0; j < 4; j++) {
            __syncwarp();
            wmma::store_matrix_sync(&Cst[warp][0], acc[i][j], 16, wmma::mem_row_major);
            __syncwarp();
            int r = rowBase + warpM * 32 + i * 16 + (lane >> 1);
            int c = warpN * 64 + j * 16 + (lane & 1) * 8;
            if (r < N_NODES) {
                const float* row = &Cst[warp][(lane >> 1) * 16 + (lane & 1) * 8];
                float v[8];
#pragma unroll
                for (int q = 0; q < 8; q++) {
                    float z = row[q] + b1[c + q];
                    v[q] = z > 0.f ? z : 0.f;
                }
                __half2 p0 = __floats2half2_rn(v[0], v[1]);
                __half2 p1 = __floats2half2_rn(v[2], v[3]);
                __half2 p2 = __floats2half2_rn(v[4], v[5]);
                __half2 p3 = __floats2half2_rn(v[6], v[7]);
                uint4 u;
                u.x = *reinterpret_cast<unsigned*>(&p0);
                u.y = *reinterpret_cast<unsigned*>(&p1);
                u.z = *reinterpret_cast<unsigned*>(&p2);
                u.w = *reinterpret_cast<unsigned*>(&p3);
                *(uint4*)(g_hh + (size_t)r * 128 + c) = u;
            }
        }
}

// [self | neigh] = g_hh @ g_B2h : K = 128.
// warpN==0 (cols 0..63, self): +b2 -> out fp32.  warpN==1: -> g_th fp16.
__global__ __launch_bounds__(256) void k_gemm2h(const float* __restrict__ b2,
                                                float* __restrict__ out) {
    __shared__ __align__(16) __half As[128][16];
    __shared__ __align__(16) __half Bs[16][128];
    __shared__ __align__(16) float  Cst[8][256];
    const int tid = threadIdx.x;
    const int warp = tid >> 5;
    const int lane = tid & 31;
    const int warpM = warp & 3;
    const int warpN = warp >> 2;
    const int rowBase = blockIdx.x * 128;

    wmma::fragment<wmma::accumulator, 16, 16, 16, float> acc[2][4];
#pragma unroll
    for (int i = 0; i < 2; i++)
#pragma unroll
        for (int j = 0; j < 4; j++) wmma::fill_fragment(acc[i][j], 0.f);

    const int aRow = tid >> 1;
    const int aCol8 = (tid & 1) * 8;
    int arow_g = rowBase + aRow;
    if (arow_g >= N_NODES) arow_g = N_NODES - 1;
    const int bRow = tid >> 4;
    const int bCol8 = (tid & 15) * 8;

    for (int kk = 0; kk < 8; kk++) {
        uint4 av = *(const uint4*)(g_hh + (size_t)arow_g * 128 + kk * 16 + aCol8);
        uint4 bv = *(const uint4*)(g_B2h + (size_t)(kk * 16 + bRow) * 128 + bCol8);
        __syncthreads();
        *(uint4*)&As[aRow][aCol8] = av;
        *(uint4*)&Bs[bRow][bCol8] = bv;
        __syncthreads();

        wmma::fragment<wmma::matrix_b, 16, 16, 16, __half, wmma::row_major> bf[4];
#pragma unroll
        for (int j = 0; j < 4; j++)
            wmma::load_matrix_sync(bf[j], &Bs[0][warpN * 64 + j * 16], 128);
#pragma unroll
        for (int i = 0; i < 2; i++) {
            wmma::fragment<wmma::matrix_a, 16, 16, 16, __half, wmma::row_major> af;
            wmma::load_matrix_sync(af, &As[warpM * 32 + i * 16][0], 16);
#pragma unroll
            for (int j = 0; j < 4; j++)
                wmma::mma_sync(acc[i][j], af, bf[j], acc[i][j]);
        }
    }

#pragma unroll
    for (int i = 0; i < 2; i++)
#pragma unroll
        for (int j = 0; j < 4; j++) {
            __syncwarp();
            wmma::store_matrix_sync(&Cst[warp][0], acc[i][j], 16, wmma::mem_row_major);
            __syncwarp();
            int r = rowBase + warpM * 32 + i * 16 + (lane >> 1);
            int cc = j * 16 + (lane & 1) * 8;     // 0..63 within half
            if (r < N_NODES) {
                const float* row = &Cst[warp][(lane >> 1) * 16 + (lane & 1) * 8];
                if (warpN == 0) {                 // self half -> fp32 out
                    float v[8];
#pragma unroll
                    for (int q = 0; q < 8; q++) v[q] = row[q] + b2[cc + q];
                    float4* dst4 = (float4*)(out + (size_t)r * D_OUT + cc);
                    dst4[0] = make_float4(v[0], v[1], v[2], v[3]);
                    dst4[1] = make_float4(v[4], v[5], v[6], v[7]);
                } else {                          // neigh half -> fp16 g_th
                    __half2 p0 = __floats2half2_rn(row[0], row[1]);
                    __half2 p1 = __floats2half2_rn(row[2], row[3]);
                    __half2 p2 = __floats2half2_rn(row[4], row[5]);
                    __half2 p3 = __floats2half2_rn(row[6], row[7]);
                    uint4 u;
                    u.x = *reinterpret_cast<unsigned*>(&p0);
                    u.y = *reinterpret_cast<unsigned*>(&p1);
                    u.z = *reinterpret_cast<unsigned*>(&p2);
                    u.w = *reinterpret_cast<unsigned*>(&p3);
                    *(uint4*)(g_th + (size_t)r * D_OUT + cc) = u;
                }
            }
        }
}

// ---------------------------------------------------------------------------
extern "C" void kernel_launch(void* const* d_in, const int* in_sizes, int n_in,
                              void* d_out, int out_size) {
    const float* x   = (const float*)d_in[0];
    const void*  src = d_in[1];
    const void*  dst = d_in[2];
    const float* Ws1 = (const float*)d_in[3];
    const float* Wn1 = (const float*)d_in[4];
    const float* b1  = (const float*)d_in[5];
    const float* Ws2 = (const float*)d_in[6];
    const float* Wn2 = (const float*)d_in[7];
    const float* b2  = (const float*)d_in[8];
    float* out = (float*)d_out;

    // 1) fused init (zero deg/flags + dtype detect + x->fp16 + W->fp16)
    k_init<<<(XCONV_T + 255) / 256, 256>>>(src, x, Ws1, Wn1, Ws2, Wn2);

    // 2) CSR build (single-pass scan)
    k_hist<<<(N_EDGES + 255) / 256, 256>>>(dst);
    k_scan_one<<<SCAN_NB, 128>>>();
    k_scatter<<<(N_EDGES + 255) / 256, 256>>>(src, dst);

    // 3) layer 1
    k_agg128h<<<(N_NODES * 32 + 255) / 256, 256>>>();
    k_gemm1h<<<(N_NODES + 127) / 128, 256>>>(b1);

    // 4) layer 2 (transform first, aggregate fp16 64-wide afterwards)
    k_gemm2h<<<(N_NODES + 127) / 128, 256>>>(b2, out);
    k_agg64h<<<(N_NODES * 32 + 255) / 256, 256>>>(out);
}